// round 6
// baseline (speedup 1.0000x reference)
#include <cuda_runtime.h>
#include <stdint.h>

// ---------------------------------------------------------------------------
// _multiCodebookQuantization: N=16, M=4, D=32, K=256, H=W=64
// outputs (concatenated, f32): sample (n,m,h,w,k) | code (n,m,h,w) | logit (n,m,h,w,k)
// R5: TPB 128->256 (occ 31.6%->~75%), fuse sample zero-fill into main kernel.
//     All numerics bit-identical to the R4 passing kernel.
// ---------------------------------------------------------------------------

#define RNG_MODE 0

static constexpr int   TPB          = 256;
static constexpr long  SAMPLE_ELEMS = 67108864L;   // 16*4*64*64*256
static constexpr long  CODE_ELEMS   = 262144L;     // 16*4*64*64
static constexpr unsigned HALF_T    = 33554432u;

// --- accurate logf (~0.85 ulp, FMA-only polynomial; input positive, normal) ---
__device__ __forceinline__ float alogf(float a) {
    int   e = (__float_as_int(a) - 0x3f2aaaab) & 0xff800000;
    float m = __int_as_float(__float_as_int(a) - e);
    float i = (float)e * 1.19209290e-7f;        // e * 2^-23
    m = m - 1.0f;
    float s = m * m;
    float r = -0.130310059f;
    float t =  0.140869141f;
    r = fmaf(r, s, -0.121483512f);
    t = fmaf(t, s,  0.139814854f);
    r = fmaf(r, s, -0.166846126f);
    t = fmaf(t, s,  0.200120345f);
    r = fmaf(r, s, -0.249996200f);
    r = fmaf(t, m, r);
    r = fmaf(r, m,  0.333331972f);
    r = fmaf(r, m, -0.500000000f);
    r = fmaf(r, s, m);
    r = fmaf(i, 0.693147182f, r);
    return r;
}

// --- Threefry-2x32, 20 rounds, key = (0, 42) (jax.random.key(42)) ---
__device__ __forceinline__ void threefry42(uint32_t x0, uint32_t x1,
                                           uint32_t& o0, uint32_t& o1) {
    const uint32_t ks1 = 42u;
    const uint32_t ks2 = 0x1BD11BDAu ^ 42u;   // ks0 = 0
    x1 += ks1;
#define TFR(r) { x0 += x1; x1 = __funnelshift_l(x1, x1, (r)); x1 ^= x0; }
    TFR(13) TFR(15) TFR(26) TFR(6)
    x0 += ks1; x1 += ks2 + 1u;
    TFR(17) TFR(29) TFR(16) TFR(24)
    x0 += ks2; x1 += 2u;
    TFR(13) TFR(15) TFR(26) TFR(6)
    x1 += ks1 + 3u;
    TFR(17) TFR(29) TFR(16) TFR(24)
    x0 += ks1; x1 += ks2 + 4u;
    TFR(13) TFR(15) TFR(26) TFR(6)
    x0 += ks2; x1 += 5u;
#undef TFR
    o0 = x0; o1 = x1;
}

__device__ __forceinline__ uint32_t gumbel_bits(uint32_t i) {
    uint32_t r0, r1;
#if RNG_MODE == 0
    threefry42(0u, i, r0, r1);
    return r0 ^ r1;
#elif RNG_MODE == 1
    threefry42(0u, i, r0, r1);
    return r0;
#elif RNG_MODE == 2
    threefry42(0u, i, r0, r1);
    return r1;
#else
    if (i < HALF_T) { threefry42(i, i + HALF_T, r0, r1); return r0; }
    else            { threefry42(i - HALF_T, i, r0, r1); return r1; }
#endif
}

// JAX gumbel: u = max(tiny, uniform_bits + tiny); g = -log(-log(u))
__device__ __forceinline__ float gumbel_from_bits(uint32_t bits) {
    float f = __uint_as_float((bits >> 9) | 0x3F800000u) - 1.0f;  // [0,1)
    float u = fmaxf(1.17549435e-38f, f + 1.17549435e-38f);
    float e = -alogf(u);
    return -alogf(e);
}

// ---------------------------------------------------------------------------
__global__ __launch_bounds__(TPB)
void mcq_main(const float* __restrict__ x,
              const float* __restrict__ cbg,
              float* __restrict__ out_sample,
              float* __restrict__ out_code,
              float* __restrict__ out_logit) {
    __shared__ float cb_s[256 * 32];   // codebook[m], row-major [k][d]
    __shared__ float c2_s[256];

    const int tid  = threadIdx.x;
    const int b    = blockIdx.x;        // 0..1023
    const int tile = b & 15;            // 16 tiles of 256 hw positions
    const int m    = (b >> 4) & 3;
    const int n    = b >> 6;            // 0..15

    // load codebook slice for m (8192 floats = 2048 float4) into smem
    const float4* cbm4 = reinterpret_cast<const float4*>(cbg + (size_t)m * 256 * 32);
    float4* cb_s4 = reinterpret_cast<float4*>(cb_s);
    #pragma unroll
    for (int i = tid; i < 2048; i += TPB) cb_s4[i] = cbm4[i];
    __syncthreads();

    // c2[k] = sum_d cb[k][d]^2  (plain mul+add, mimicking XLA's mul-then-reduce)
    for (int k = tid; k < 256; k += TPB) {
        float s = 0.f;
        #pragma unroll
        for (int d = 0; d < 32; d++)
            s = __fadd_rn(s, __fmul_rn(cb_s[k * 32 + d], cb_s[k * 32 + d]));
        c2_s[k] = s;
    }
    __syncthreads();

    const int hw  = tile * TPB + tid;               // 0..4095
    const int pos = (n * 4 + m) * 4096 + hw;        // flat (n,m,h,w)

    // load x vector (32 channels, stride H*W) + x2
    const float* xp = x + ((size_t)(n * 128 + m * 32)) * 4096 + hw;
    float xa[32];
    float x2 = 0.f;
    #pragma unroll
    for (int d = 0; d < 32; d++) {
        xa[d] = xp[(size_t)d * 4096];
        x2 = __fadd_rn(x2, __fmul_rn(xa[d], xa[d]));
    }

    const float4* cb4 = reinterpret_cast<const float4*>(cb_s);
    float4* lrow4 = reinterpret_cast<float4*>(out_logit  + (size_t)pos * 256);
    float4* srow4 = reinterpret_cast<float4*>(out_sample + (size_t)pos * 256);
    const uint32_t ctr0 = (uint32_t)pos * 256u;
    const float4 zero4 = make_float4(0.f, 0.f, 0.f, 0.f);

    float best = -1e38f, bdist = 1.f, sum = 0.f;
    int   bidx = 0;

    #pragma unroll 1
    for (int k4 = 0; k4 < 64; k4++) {
        float4 lv;
        #pragma unroll
        for (int j = 0; j < 4; j++) {
            const int k = k4 * 4 + j;
            // dot(x, codebook[k]) with 4 partial sums
            float d0 = 0.f, d1 = 0.f, d2 = 0.f, d3 = 0.f;
            #pragma unroll
            for (int q = 0; q < 8; q++) {
                float4 c = cb4[k * 8 + q];
                d0 = fmaf(xa[4 * q + 0], c.x, d0);
                d1 = fmaf(xa[4 * q + 1], c.y, d1);
                d2 = fmaf(xa[4 * q + 2], c.z, d2);
                d3 = fmaf(xa[4 * q + 3], c.w, d3);
            }
            const float dot  = (d0 + d1) + (d2 + d3);
            const float dist = fmaf(-2.0f, dot, __fadd_rn(x2, c2_s[k]));
            sum += dist;

            const float l = alogf(dist);               // logit output + decision
            (&lv.x)[j] = l;

            const float g = gumbel_from_bits(gumbel_bits(ctr0 + (uint32_t)k));
            const float v = l + g;
            if (v > best) { best = v; bidx = k; bdist = dist; }
        }
        lrow4[k4] = lv;       // logits
        srow4[k4] = zero4;    // fused zero-fill of sample row (one-hot set below)
    }

    // probs[idx] = softmax(log dist)[idx] == dist_idx / sum(dist)
    const float p = bdist / sum;
    out_sample[(size_t)pos * 256 + bidx] = (1.0f + p) - p;  // hard + probs - sg(probs)
    out_code[pos] = (float)bidx;
}

// ---------------------------------------------------------------------------
extern "C" void kernel_launch(void* const* d_in, const int* in_sizes, int n_in,
                              void* d_out, int out_size) {
    const float* x  = (const float*)d_in[0];   // (16, 128, 64, 64) f32
    const float* cb = (const float*)d_in[1];   // (4, 256, 32)      f32

    float* out        = (float*)d_out;
    float* out_sample = out;                                  // 67,108,864
    float* out_code   = out + SAMPLE_ELEMS;                   //    262,144
    float* out_logit  = out + SAMPLE_ELEMS + CODE_ELEMS;      // 67,108,864

    // single fused kernel: distances, logits, threefry gumbel-max,
    // sample zero-fill + one-hot, code
    mcq_main<<<1024, TPB>>>(x, cb, out_sample, out_code, out_logit);
}

// round 7
// speedup vs baseline: 1.1047x; 1.1047x over previous
#include <cuda_runtime.h>
#include <stdint.h>

// ---------------------------------------------------------------------------
// _multiCodebookQuantization: N=16, M=4, D=32, K=256, H=W=64
// outputs (concatenated, f32): sample (n,m,h,w,k) | code (n,m,h,w) | logit (n,m,h,w,k)
// R7: revert R6 store-fusion (regressed); occupancy push:
//     - codebook processed in 2 chunks of 128 k (smem 33.8KB -> ~17KB)
//     - __launch_bounds__(128, 8) => <=64 regs => 32 warps/SM (50% occ)
//     - bdist/c2[bidx] recomputed after the loop (bit-identical op order)
//     All arithmetic bit-identical to the R4/R5 passing kernel.
// ---------------------------------------------------------------------------

#define RNG_MODE 0

static constexpr int   TPB          = 128;
static constexpr long  SAMPLE_ELEMS = 67108864L;   // 16*4*64*64*256
static constexpr long  CODE_ELEMS   = 262144L;     // 16*4*64*64
static constexpr unsigned HALF_T    = 33554432u;
static constexpr int   KCHUNK       = 128;         // k's per smem chunk

// --- accurate logf (~0.85 ulp, FMA-only polynomial; input positive, normal) ---
__device__ __forceinline__ float alogf(float a) {
    int   e = (__float_as_int(a) - 0x3f2aaaab) & 0xff800000;
    float m = __int_as_float(__float_as_int(a) - e);
    float i = (float)e * 1.19209290e-7f;        // e * 2^-23
    m = m - 1.0f;
    float s = m * m;
    float r = -0.130310059f;
    float t =  0.140869141f;
    r = fmaf(r, s, -0.121483512f);
    t = fmaf(t, s,  0.139814854f);
    r = fmaf(r, s, -0.166846126f);
    t = fmaf(t, s,  0.200120345f);
    r = fmaf(r, s, -0.249996200f);
    r = fmaf(t, m, r);
    r = fmaf(r, m,  0.333331972f);
    r = fmaf(r, m, -0.500000000f);
    r = fmaf(r, s, m);
    r = fmaf(i, 0.693147182f, r);
    return r;
}

// --- Threefry-2x32, 20 rounds, key = (0, 42) (jax.random.key(42)) ---
__device__ __forceinline__ void threefry42(uint32_t x0, uint32_t x1,
                                           uint32_t& o0, uint32_t& o1) {
    const uint32_t ks1 = 42u;
    const uint32_t ks2 = 0x1BD11BDAu ^ 42u;   // ks0 = 0
    x1 += ks1;
#define TFR(r) { x0 += x1; x1 = __funnelshift_l(x1, x1, (r)); x1 ^= x0; }
    TFR(13) TFR(15) TFR(26) TFR(6)
    x0 += ks1; x1 += ks2 + 1u;
    TFR(17) TFR(29) TFR(16) TFR(24)
    x0 += ks2; x1 += 2u;
    TFR(13) TFR(15) TFR(26) TFR(6)
    x1 += ks1 + 3u;
    TFR(17) TFR(29) TFR(16) TFR(24)
    x0 += ks1; x1 += ks2 + 4u;
    TFR(13) TFR(15) TFR(26) TFR(6)
    x0 += ks2; x1 += 5u;
#undef TFR
    o0 = x0; o1 = x1;
}

__device__ __forceinline__ uint32_t gumbel_bits(uint32_t i) {
    uint32_t r0, r1;
#if RNG_MODE == 0
    threefry42(0u, i, r0, r1);
    return r0 ^ r1;
#elif RNG_MODE == 1
    threefry42(0u, i, r0, r1);
    return r0;
#elif RNG_MODE == 2
    threefry42(0u, i, r0, r1);
    return r1;
#else
    if (i < HALF_T) { threefry42(i, i + HALF_T, r0, r1); return r0; }
    else            { threefry42(i - HALF_T, i, r0, r1); return r1; }
#endif
}

// JAX gumbel: u = max(tiny, uniform_bits + tiny); g = -log(-log(u))
__device__ __forceinline__ float gumbel_from_bits(uint32_t bits) {
    float f = __uint_as_float((bits >> 9) | 0x3F800000u) - 1.0f;  // [0,1)
    float u = fmaxf(1.17549435e-38f, f + 1.17549435e-38f);
    float e = -alogf(u);
    return -alogf(e);
}

// ---------------------------------------------------------------------------
__global__ void mcq_zerofill(float4* __restrict__ p) {
    size_t i = (size_t)blockIdx.x * blockDim.x + threadIdx.x;
    p[i] = make_float4(0.f, 0.f, 0.f, 0.f);
}

__global__ __launch_bounds__(TPB, 8)
void mcq_main(const float* __restrict__ x,
              const float* __restrict__ cbg,
              float* __restrict__ out_sample,
              float* __restrict__ out_code,
              float* __restrict__ out_logit) {
    __shared__ float cb_s[KCHUNK * 32];   // codebook chunk, row-major [k][d]
    __shared__ float c2_s[KCHUNK];

    const int tid  = threadIdx.x;
    const int b    = blockIdx.x;        // 0..2047
    const int tile = b & 31;            // 32 tiles of 128 hw positions
    const int m    = (b >> 5) & 3;
    const int n    = b >> 7;            // 0..15

    const int hw  = tile * TPB + tid;               // 0..4095
    const int pos = (n * 4 + m) * 4096 + hw;        // flat (n,m,h,w)

    // load x vector (32 channels, stride H*W) + x2
    const float* xp = x + ((size_t)(n * 128 + m * 32)) * 4096 + hw;
    float xa[32];
    float x2 = 0.f;
    #pragma unroll
    for (int d = 0; d < 32; d++) {
        xa[d] = xp[(size_t)d * 4096];
        x2 = __fadd_rn(x2, __fmul_rn(xa[d], xa[d]));
    }

    const float4* cb4 = reinterpret_cast<const float4*>(cb_s);
    float4* lrow4 = reinterpret_cast<float4*>(out_logit + (size_t)pos * 256);
    const uint32_t ctr0 = (uint32_t)pos * 256u;

    float best = -1e38f, sum = 0.f;
    int   bidx = 0;

    #pragma unroll 1
    for (int c = 0; c < 2; c++) {
        // load codebook chunk for (m, c): 128 k x 32 d = 1024 float4
        __syncthreads();   // previous chunk fully consumed
        const float4* cbm4 = reinterpret_cast<const float4*>(
            cbg + (size_t)m * 256 * 32 + (size_t)c * KCHUNK * 32);
        float4* cb_s4 = reinterpret_cast<float4*>(cb_s);
        #pragma unroll
        for (int i = tid; i < KCHUNK * 8; i += TPB) cb_s4[i] = cbm4[i];
        __syncthreads();

        // c2[k] = sum_d cb[k][d]^2 (one k per thread; same op order as before)
        {
            float s = 0.f;
            #pragma unroll
            for (int d = 0; d < 32; d++)
                s = __fadd_rn(s, __fmul_rn(cb_s[tid * 32 + d], cb_s[tid * 32 + d]));
            c2_s[tid] = s;
        }
        __syncthreads();

        #pragma unroll 1
        for (int k4 = 0; k4 < KCHUNK / 4; k4++) {
            float4 lv;
            #pragma unroll
            for (int j = 0; j < 4; j++) {
                const int kl = k4 * 4 + j;            // local k in chunk
                const int k  = c * KCHUNK + kl;       // global k (ascending)
                // dot(x, codebook[k]) with 4 partial sums
                float d0 = 0.f, d1 = 0.f, d2 = 0.f, d3 = 0.f;
                #pragma unroll
                for (int q = 0; q < 8; q++) {
                    float4 cc = cb4[kl * 8 + q];
                    d0 = fmaf(xa[4 * q + 0], cc.x, d0);
                    d1 = fmaf(xa[4 * q + 1], cc.y, d1);
                    d2 = fmaf(xa[4 * q + 2], cc.z, d2);
                    d3 = fmaf(xa[4 * q + 3], cc.w, d3);
                }
                const float dot  = (d0 + d1) + (d2 + d3);
                const float dist = fmaf(-2.0f, dot, __fadd_rn(x2, c2_s[kl]));
                sum += dist;

                const float l = alogf(dist);          // logit output + decision
                (&lv.x)[j] = l;

                const float g = gumbel_from_bits(gumbel_bits(ctr0 + (uint32_t)k));
                const float v = l + g;
                if (v > best) { best = v; bidx = k; }
            }
            lrow4[c * (KCHUNK / 4) + k4] = lv;        // coalesced float4 logit store
        }
    }

    // Recompute winning dist with identical op order (chunk smem is gone).
    float bdist;
    {
        const float* cr = cbg + (size_t)m * 256 * 32 + (size_t)bidx * 32;
        float cw[32];
        #pragma unroll
        for (int d = 0; d < 32; d++) cw[d] = __ldg(cr + d);
        float s = 0.f;
        #pragma unroll
        for (int d = 0; d < 32; d++)
            s = __fadd_rn(s, __fmul_rn(cw[d], cw[d]));    // c2, same order
        float d0 = 0.f, d1 = 0.f, d2 = 0.f, d3 = 0.f;
        #pragma unroll
        for (int q = 0; q < 8; q++) {
            d0 = fmaf(xa[4 * q + 0], cw[4 * q + 0], d0);
            d1 = fmaf(xa[4 * q + 1], cw[4 * q + 1], d1);
            d2 = fmaf(xa[4 * q + 2], cw[4 * q + 2], d2);
            d3 = fmaf(xa[4 * q + 3], cw[4 * q + 3], d3);
        }
        const float dot = (d0 + d1) + (d2 + d3);
        bdist = fmaf(-2.0f, dot, __fadd_rn(x2, s));
    }

    // probs[idx] = softmax(log dist)[idx] == dist_idx / sum(dist)
    const float p = bdist / sum;
    out_sample[(size_t)pos * 256 + bidx] = (1.0f + p) - p;  // hard + probs - sg(probs)
    out_code[pos] = (float)bidx;
}

// ---------------------------------------------------------------------------
extern "C" void kernel_launch(void* const* d_in, const int* in_sizes, int n_in,
                              void* d_out, int out_size) {
    const float* x  = (const float*)d_in[0];   // (16, 128, 64, 64) f32
    const float* cb = (const float*)d_in[1];   // (4, 256, 32)      f32

    float* out        = (float*)d_out;
    float* out_sample = out;                                  // 67,108,864
    float* out_code   = out + SAMPLE_ELEMS;                   //    262,144
    float* out_logit  = out + SAMPLE_ELEMS + CODE_ELEMS;      // 67,108,864

    // zero the one-hot sample region at full bandwidth (16,777,216 float4)
    mcq_zerofill<<<65536, 256>>>((float4*)out_sample);
    // main fused kernel: distances, logits, threefry gumbel-max, one-hot, code
    mcq_main<<<2048, TPB>>>(x, cb, out_sample, out_code, out_logit);
}

// round 9
// speedup vs baseline: 1.1604x; 1.0504x over previous
#include <cuda_runtime.h>
#include <stdint.h>

// ---------------------------------------------------------------------------
// _multiCodebookQuantization: N=16, M=4, D=32, K=256, H=W=64
// outputs (concatenated, f32): sample (n,m,h,w,k) | code (n,m,h,w) | logit (n,m,h,w,k)
// R9: REVERT R8 race (one argmax flip -> rel_err 2.8e-3). Loop numerics are
//     bit-identical to the R4/R5 passing kernel (rel_err 4e-8, 3x verified):
//     full l+g decision with all three fp32 log roundings.
//     Structural change only: sample zero-fill + one-hot moved into a
//     post-loop tail burst (overlaps other blocks' ALU-bound compute),
//     eliminating the dedicated 48us zerofill launch.
// ---------------------------------------------------------------------------

#define RNG_MODE 0

static constexpr int   TPB          = 128;
static constexpr long  SAMPLE_ELEMS = 67108864L;   // 16*4*64*64*256
static constexpr long  CODE_ELEMS   = 262144L;     // 16*4*64*64
static constexpr unsigned HALF_T    = 33554432u;

// --- accurate logf (~0.85 ulp, FMA-only polynomial; input positive, normal) ---
__device__ __forceinline__ float alogf(float a) {
    int   e = (__float_as_int(a) - 0x3f2aaaab) & 0xff800000;
    float m = __int_as_float(__float_as_int(a) - e);
    float i = (float)e * 1.19209290e-7f;        // e * 2^-23
    m = m - 1.0f;
    float s = m * m;
    float r = -0.130310059f;
    float t =  0.140869141f;
    r = fmaf(r, s, -0.121483512f);
    t = fmaf(t, s,  0.139814854f);
    r = fmaf(r, s, -0.166846126f);
    t = fmaf(t, s,  0.200120345f);
    r = fmaf(r, s, -0.249996200f);
    r = fmaf(t, m, r);
    r = fmaf(r, m,  0.333331972f);
    r = fmaf(r, m, -0.500000000f);
    r = fmaf(r, s, m);
    r = fmaf(i, 0.693147182f, r);
    return r;
}

// --- Threefry-2x32, 20 rounds, key = (0, 42) (jax.random.key(42)) ---
__device__ __forceinline__ void threefry42(uint32_t x0, uint32_t x1,
                                           uint32_t& o0, uint32_t& o1) {
    const uint32_t ks1 = 42u;
    const uint32_t ks2 = 0x1BD11BDAu ^ 42u;   // ks0 = 0
    x1 += ks1;
#define TFR(r) { x0 += x1; x1 = __funnelshift_l(x1, x1, (r)); x1 ^= x0; }
    TFR(13) TFR(15) TFR(26) TFR(6)
    x0 += ks1; x1 += ks2 + 1u;
    TFR(17) TFR(29) TFR(16) TFR(24)
    x0 += ks2; x1 += 2u;
    TFR(13) TFR(15) TFR(26) TFR(6)
    x1 += ks1 + 3u;
    TFR(17) TFR(29) TFR(16) TFR(24)
    x0 += ks1; x1 += ks2 + 4u;
    TFR(13) TFR(15) TFR(26) TFR(6)
    x0 += ks2; x1 += 5u;
#undef TFR
    o0 = x0; o1 = x1;
}

__device__ __forceinline__ uint32_t gumbel_bits(uint32_t i) {
    uint32_t r0, r1;
#if RNG_MODE == 0
    threefry42(0u, i, r0, r1);
    return r0 ^ r1;
#elif RNG_MODE == 1
    threefry42(0u, i, r0, r1);
    return r0;
#elif RNG_MODE == 2
    threefry42(0u, i, r0, r1);
    return r1;
#else
    if (i < HALF_T) { threefry42(i, i + HALF_T, r0, r1); return r0; }
    else            { threefry42(i - HALF_T, i, r0, r1); return r1; }
#endif
}

// JAX gumbel: u = max(tiny, uniform_bits + tiny); g = -log(-log(u))
// (full rounding chain — required for decision agreement with the reference)
__device__ __forceinline__ float gumbel_from_bits(uint32_t bits) {
    float f = __uint_as_float((bits >> 9) | 0x3F800000u) - 1.0f;  // [0,1)
    float u = fmaxf(1.17549435e-38f, f + 1.17549435e-38f);
    float e = -alogf(u);
    return -alogf(e);
}

// ---------------------------------------------------------------------------
__global__ __launch_bounds__(TPB)
void mcq_main(const float* __restrict__ x,
              const float* __restrict__ cbg,
              float* __restrict__ out_sample,
              float* __restrict__ out_code,
              float* __restrict__ out_logit) {
    __shared__ float cb_s[256 * 32];   // codebook[m], row-major [k][d]
    __shared__ float c2_s[256];

    const int tid  = threadIdx.x;
    const int b    = blockIdx.x;        // 0..2047
    const int tile = b & 31;            // 32 tiles of 128 hw positions
    const int m    = (b >> 5) & 3;
    const int n    = b >> 7;            // 0..15

    // load codebook slice for m (8192 floats = 2048 float4) into smem
    const float4* cbm4 = reinterpret_cast<const float4*>(cbg + (size_t)m * 256 * 32);
    float4* cb_s4 = reinterpret_cast<float4*>(cb_s);
    #pragma unroll
    for (int i = tid; i < 2048; i += TPB) cb_s4[i] = cbm4[i];
    __syncthreads();

    // c2[k] = sum_d cb[k][d]^2  (plain mul+add, mimicking XLA's mul-then-reduce)
    for (int k = tid; k < 256; k += TPB) {
        float s = 0.f;
        #pragma unroll
        for (int d = 0; d < 32; d++)
            s = __fadd_rn(s, __fmul_rn(cb_s[k * 32 + d], cb_s[k * 32 + d]));
        c2_s[k] = s;
    }
    __syncthreads();

    const int hw  = tile * TPB + tid;               // 0..4095
    const int pos = (n * 4 + m) * 4096 + hw;        // flat (n,m,h,w)

    // load x vector (32 channels, stride H*W) + x2
    const float* xp = x + ((size_t)(n * 128 + m * 32)) * 4096 + hw;
    float xa[32];
    float x2 = 0.f;
    #pragma unroll
    for (int d = 0; d < 32; d++) {
        xa[d] = xp[(size_t)d * 4096];
        x2 = __fadd_rn(x2, __fmul_rn(xa[d], xa[d]));
    }

    const float4* cb4 = reinterpret_cast<const float4*>(cb_s);
    float4* lrow4 = reinterpret_cast<float4*>(out_logit + (size_t)pos * 256);
    const uint32_t ctr0 = (uint32_t)pos * 256u;

    float best = -1e38f, bdist = 1.f, sum = 0.f;
    int   bidx = 0;

    #pragma unroll 1
    for (int k4 = 0; k4 < 64; k4++) {
        float4 lv;
        #pragma unroll
        for (int j = 0; j < 4; j++) {
            const int k = k4 * 4 + j;
            // dot(x, codebook[k]) with 4 partial sums
            float d0 = 0.f, d1 = 0.f, d2 = 0.f, d3 = 0.f;
            #pragma unroll
            for (int q = 0; q < 8; q++) {
                float4 c = cb4[k * 8 + q];
                d0 = fmaf(xa[4 * q + 0], c.x, d0);
                d1 = fmaf(xa[4 * q + 1], c.y, d1);
                d2 = fmaf(xa[4 * q + 2], c.z, d2);
                d3 = fmaf(xa[4 * q + 3], c.w, d3);
            }
            const float dot  = (d0 + d1) + (d2 + d3);
            const float dist = fmaf(-2.0f, dot, __fadd_rn(x2, c2_s[k]));
            sum += dist;

            const float l = alogf(dist);               // logit output + decision
            (&lv.x)[j] = l;

            const float g = gumbel_from_bits(gumbel_bits(ctr0 + (uint32_t)k));
            const float v = l + g;
            if (v > best) { best = v; bidx = k; bdist = dist; }
        }
        lrow4[k4] = lv;   // coalesced-row float4 store of logits
    }

    // --- tail: fused sample writeout (zeros + one-hot), code ---
    // Burst of 64 STG.128 after compute: overlaps other blocks' ALU work.
    float4* srow4 = reinterpret_cast<float4*>(out_sample + (size_t)pos * 256);
    const float4 zero4 = make_float4(0.f, 0.f, 0.f, 0.f);
    #pragma unroll 8
    for (int q = 0; q < 64; q++) srow4[q] = zero4;

    // probs[idx] = softmax(log dist)[idx] == dist_idx / sum(dist)
    const float p = bdist / sum;
    // same-thread, same-address ordering: scalar store lands after the zeros
    out_sample[(size_t)pos * 256 + bidx] = (1.0f + p) - p;  // hard + probs - sg(probs)
    out_code[pos] = (float)bidx;
}

// ---------------------------------------------------------------------------
extern "C" void kernel_launch(void* const* d_in, const int* in_sizes, int n_in,
                              void* d_out, int out_size) {
    const float* x  = (const float*)d_in[0];   // (16, 128, 64, 64) f32
    const float* cb = (const float*)d_in[1];   // (4, 256, 32)      f32

    float* out        = (float*)d_out;
    float* out_sample = out;                                  // 67,108,864
    float* out_code   = out + SAMPLE_ELEMS;                   //    262,144
    float* out_logit  = out + SAMPLE_ELEMS + CODE_ELEMS;      // 67,108,864

    // single fused kernel: distances, logits, threefry gumbel-max,
    // tail sample zero+one-hot, code
    mcq_main<<<2048, TPB>>>(x, cb, out_sample, out_code, out_logit);
}

// round 10
// speedup vs baseline: 1.1828x; 1.0194x over previous
#include <cuda_runtime.h>
#include <stdint.h>

// ---------------------------------------------------------------------------
// _multiCodebookQuantization: N=16, M=4, D=32, K=256, H=W=64
// outputs (concatenated, f32): sample (n,m,h,w,k) | code (n,m,h,w) | logit (n,m,h,w,k)
// R10: attack wave-quantization tail. TPB 256 = 128 positions x 2 k-halves:
//      thread t handles k in [0,128), thread t+128 handles k in [128,256) for
//      the same position, each with the BIT-IDENTICAL R4/R5 per-k pipeline
//      (rel_err 4e-8, 4x verified). Post-loop merge via smem reproduces the
//      ascending strict-> scan exactly. Block duration halves: waves
//      2.31 -> 4.61, tail waste ~161us -> ~40us.
//      Zerofill stays a separate kernel (R6/R9 fusions both regressed).
// ---------------------------------------------------------------------------

#define RNG_MODE 0

static constexpr int   TPB          = 256;   // 128 positions x 2 k-halves
static constexpr int   POSB         = 128;   // positions per block
static constexpr long  SAMPLE_ELEMS = 67108864L;   // 16*4*64*64*256
static constexpr long  CODE_ELEMS   = 262144L;     // 16*4*64*64
static constexpr unsigned HALF_T    = 33554432u;

// --- accurate logf (~0.85 ulp, FMA-only polynomial; input positive, normal) ---
__device__ __forceinline__ float alogf(float a) {
    int   e = (__float_as_int(a) - 0x3f2aaaab) & 0xff800000;
    float m = __int_as_float(__float_as_int(a) - e);
    float i = (float)e * 1.19209290e-7f;        // e * 2^-23
    m = m - 1.0f;
    float s = m * m;
    float r = -0.130310059f;
    float t =  0.140869141f;
    r = fmaf(r, s, -0.121483512f);
    t = fmaf(t, s,  0.139814854f);
    r = fmaf(r, s, -0.166846126f);
    t = fmaf(t, s,  0.200120345f);
    r = fmaf(r, s, -0.249996200f);
    r = fmaf(t, m, r);
    r = fmaf(r, m,  0.333331972f);
    r = fmaf(r, m, -0.500000000f);
    r = fmaf(r, s, m);
    r = fmaf(i, 0.693147182f, r);
    return r;
}

// --- Threefry-2x32, 20 rounds, key = (0, 42) (jax.random.key(42)) ---
__device__ __forceinline__ void threefry42(uint32_t x0, uint32_t x1,
                                           uint32_t& o0, uint32_t& o1) {
    const uint32_t ks1 = 42u;
    const uint32_t ks2 = 0x1BD11BDAu ^ 42u;   // ks0 = 0
    x1 += ks1;
#define TFR(r) { x0 += x1; x1 = __funnelshift_l(x1, x1, (r)); x1 ^= x0; }
    TFR(13) TFR(15) TFR(26) TFR(6)
    x0 += ks1; x1 += ks2 + 1u;
    TFR(17) TFR(29) TFR(16) TFR(24)
    x0 += ks2; x1 += 2u;
    TFR(13) TFR(15) TFR(26) TFR(6)
    x1 += ks1 + 3u;
    TFR(17) TFR(29) TFR(16) TFR(24)
    x0 += ks1; x1 += ks2 + 4u;
    TFR(13) TFR(15) TFR(26) TFR(6)
    x0 += ks2; x1 += 5u;
#undef TFR
    o0 = x0; o1 = x1;
}

__device__ __forceinline__ uint32_t gumbel_bits(uint32_t i) {
    uint32_t r0, r1;
#if RNG_MODE == 0
    threefry42(0u, i, r0, r1);
    return r0 ^ r1;
#elif RNG_MODE == 1
    threefry42(0u, i, r0, r1);
    return r0;
#elif RNG_MODE == 2
    threefry42(0u, i, r0, r1);
    return r1;
#else
    if (i < HALF_T) { threefry42(i, i + HALF_T, r0, r1); return r0; }
    else            { threefry42(i - HALF_T, i, r0, r1); return r1; }
#endif
}

// JAX gumbel: u = max(tiny, uniform_bits + tiny); g = -log(-log(u))
// (full rounding chain — required for decision agreement with the reference)
__device__ __forceinline__ float gumbel_from_bits(uint32_t bits) {
    float f = __uint_as_float((bits >> 9) | 0x3F800000u) - 1.0f;  // [0,1)
    float u = fmaxf(1.17549435e-38f, f + 1.17549435e-38f);
    float e = -alogf(u);
    return -alogf(e);
}

// ---------------------------------------------------------------------------
__global__ void mcq_zerofill(float4* __restrict__ p) {
    size_t i = (size_t)blockIdx.x * blockDim.x + threadIdx.x;
    p[i] = make_float4(0.f, 0.f, 0.f, 0.f);
}

__global__ __launch_bounds__(TPB, 3)
void mcq_main(const float* __restrict__ x,
              const float* __restrict__ cbg,
              float* __restrict__ out_sample,
              float* __restrict__ out_code,
              float* __restrict__ out_logit) {
    __shared__ float cb_s[256 * 32];   // full codebook[m], row-major [k][d]
    __shared__ float c2_s[256];
    __shared__ float s_best[POSB];     // half-1 race state for merge
    __shared__ float s_bdist[POSB];
    __shared__ float s_sum[POSB];
    __shared__ int   s_bidx[POSB];

    const int tid  = threadIdx.x;       // 0..255
    const int lt   = tid & (POSB - 1);  // position lane 0..127
    const int half = tid >> 7;          // k-half: 0 -> k[0,128), 1 -> k[128,256)
    const int b    = blockIdx.x;        // 0..2047
    const int tile = b & 31;            // 32 tiles of 128 hw positions
    const int m    = (b >> 5) & 3;
    const int n    = b >> 7;            // 0..15

    // load full codebook slice for m (8192 floats = 2048 float4) into smem
    const float4* cbm4 = reinterpret_cast<const float4*>(cbg + (size_t)m * 256 * 32);
    float4* cb_s4 = reinterpret_cast<float4*>(cb_s);
    #pragma unroll
    for (int i = tid; i < 2048; i += TPB) cb_s4[i] = cbm4[i];
    __syncthreads();

    // c2[k] = sum_d cb[k][d]^2 — one k per thread, same per-k op order as R4
    {
        float s = 0.f;
        #pragma unroll
        for (int d = 0; d < 32; d++)
            s = __fadd_rn(s, __fmul_rn(cb_s[tid * 32 + d], cb_s[tid * 32 + d]));
        c2_s[tid] = s;
    }
    __syncthreads();

    const int hw  = tile * POSB + lt;               // 0..4095
    const int pos = (n * 4 + m) * 4096 + hw;        // flat (n,m,h,w)

    // load x vector (32 channels, stride H*W) + x2 (both halves: identical)
    const float* xp = x + ((size_t)(n * 128 + m * 32)) * 4096 + hw;
    float xa[32];
    float x2 = 0.f;
    #pragma unroll
    for (int d = 0; d < 32; d++) {
        xa[d] = xp[(size_t)d * 4096];
        x2 = __fadd_rn(x2, __fmul_rn(xa[d], xa[d]));
    }

    const float4* cb4 = reinterpret_cast<const float4*>(cb_s);
    float4* lrow4 = reinterpret_cast<float4*>(out_logit + (size_t)pos * 256);
    const int kbase = half * 128;
    const uint32_t ctr0 = (uint32_t)pos * 256u + (uint32_t)kbase;

    float best = -1e38f, bdist = 1.f, sum = 0.f;
    int   bidx = kbase;

    #pragma unroll 1
    for (int k4 = 0; k4 < 32; k4++) {
        float4 lv;
        #pragma unroll
        for (int j = 0; j < 4; j++) {
            const int kl = k4 * 4 + j;            // local k within half
            const int k  = kbase + kl;            // global k (ascending per half)
            // dot(x, codebook[k]) with 4 partial sums — exact R4 op order
            float d0 = 0.f, d1 = 0.f, d2 = 0.f, d3 = 0.f;
            #pragma unroll
            for (int q = 0; q < 8; q++) {
                float4 c = cb4[k * 8 + q];
                d0 = fmaf(xa[4 * q + 0], c.x, d0);
                d1 = fmaf(xa[4 * q + 1], c.y, d1);
                d2 = fmaf(xa[4 * q + 2], c.z, d2);
                d3 = fmaf(xa[4 * q + 3], c.w, d3);
            }
            const float dot  = (d0 + d1) + (d2 + d3);
            const float dist = fmaf(-2.0f, dot, __fadd_rn(x2, c2_s[k]));
            sum += dist;

            const float l = alogf(dist);               // logit output + decision
            (&lv.x)[j] = l;

            const float g = gumbel_from_bits(gumbel_bits(ctr0 + (uint32_t)kl));
            const float v = l + g;
            if (v > best) { best = v; bidx = k; bdist = dist; }
        }
        lrow4[kbase / 4 + k4] = lv;   // coalesced float4 logit store
    }

    // --- merge the two k-halves (reproduces ascending strict-> scan) ---
    if (half == 1) {
        s_best[lt]  = best;
        s_bdist[lt] = bdist;
        s_sum[lt]   = sum;
        s_bidx[lt]  = bidx;
    }
    __syncthreads();
    if (half == 0) {
        // hi wins only on strictly greater (ties keep the earlier/lower k)
        if (s_best[lt] > best) { bidx = s_bidx[lt]; bdist = s_bdist[lt]; }
        sum += s_sum[lt];   // p is ulp-insensitive: only enters (1+p)-p

        // probs[idx] = softmax(log dist)[idx] == dist_idx / sum(dist)
        const float p = bdist / sum;
        out_sample[(size_t)pos * 256 + bidx] = (1.0f + p) - p;  // hard + probs - sg(probs)
        out_code[pos] = (float)bidx;
    }
}

// ---------------------------------------------------------------------------
extern "C" void kernel_launch(void* const* d_in, const int* in_sizes, int n_in,
                              void* d_out, int out_size) {
    const float* x  = (const float*)d_in[0];   // (16, 128, 64, 64) f32
    const float* cb = (const float*)d_in[1];   // (4, 256, 32)      f32

    float* out        = (float*)d_out;
    float* out_sample = out;                                  // 67,108,864
    float* out_code   = out + SAMPLE_ELEMS;                   //    262,144
    float* out_logit  = out + SAMPLE_ELEMS + CODE_ELEMS;      // 67,108,864

    // zero the one-hot sample region at full bandwidth (16,777,216 float4)
    mcq_zerofill<<<65536, 256>>>((float4*)out_sample);
    // main kernel: distances, logits, threefry gumbel-max, one-hot, code
    // (one-hot scalar store ordered after zerofill by stream ordering)
    mcq_main<<<2048, TPB>>>(x, cb, out_sample, out_code, out_logit);
}